// round 2
// baseline (speedup 1.0000x reference)
#include <cuda_runtime.h>
#include <cuda_bf16.h>

#define HIMG 240
#define WIMG 135
#define HW   (HIMG * WIMG)
#define NF   1000
#define NV   600
#define INV_SIGMA 1.0e4f
#define BLURF 9.210240366975849e-4f

#define NB      148     // grid blocks: <= SM count -> guaranteed co-resident
#define NT      256

struct __align__(16) FaceData {
    float ax, ay, bx, by, cx, cy;
    float e0x, e0y, e1x, e1y, e2x, e2y;
    float rd0, rd1, rd2;
    int x0, x1, y0, y1;   // inclusive; x0 > x1 => skip face
};

__device__ FaceData g_face[NF];
__device__ float    g_sum[HW];
__device__ float    g_partial[NB];
__device__ unsigned g_count   = 0;   // self-resets at each barrier
__device__ unsigned g_release = 0;   // monotonic across graph replays

// Grid-wide barrier. Safe because grid (NB=148 blocks, 256 thr, tiny smem)
// is a single fully-resident wave. g_release is monotonic; compare against
// the per-launch base with wrap-safe unsigned subtraction.
__device__ __forceinline__ void grid_barrier(unsigned base, unsigned r) {
    __syncthreads();
    if (threadIdx.x == 0) {
        __threadfence();
        unsigned old = atomicAdd(&g_count, 1);
        if (old == NB - 1) {
            g_count = 0;
            __threadfence();
            atomicAdd(&g_release, 1);
        } else {
            while (atomicAdd(&g_release, 0) - base < r) { }
        }
        __threadfence();
    }
    __syncthreads();
}

__device__ __forceinline__ float block_reduce(float v, float* ws) {
#pragma unroll
    for (int o = 16; o > 0; o >>= 1)
        v += __shfl_down_sync(0xffffffffu, v, o);
    int lane = threadIdx.x & 31;
    int wid  = threadIdx.x >> 5;
    if (lane == 0) ws[wid] = v;
    __syncthreads();
    if (wid == 0) {
        v = (lane < (NT >> 5)) ? ws[lane] : 0.0f;
#pragma unroll
        for (int o = 4; o > 0; o >>= 1)
            v += __shfl_down_sync(0xffu, v, o);
    }
    return v;   // valid in thread 0
}

__global__ void __launch_bounds__(NT, 1)
fused_kernel(const float* __restrict__ verts,
             const int*   __restrict__ faces,
             const float* __restrict__ gt,
             float* __restrict__ out /* [0]=loss, [1..]=sil */) {
    __shared__ float    ws[8];
    __shared__ unsigned s_base;

    const int tid  = threadIdx.x;
    const int bid  = blockIdx.x;
    const int gtid = bid * NT + tid;

    if (tid == 0) s_base = atomicAdd(&g_release, 0u);
    __syncthreads();
    const unsigned base = s_base;

    // ---------------- Phase 1: zero accumulators + per-face prep -----------
    if (gtid < HW) g_sum[gtid] = 0.0f;

    if (gtid < NF) {
        const int f = gtid;
        int i0 = faces[3 * f + 0];
        int i1 = faces[3 * f + 1];
        int i2 = faces[3 * f + 2];
        int idx[3] = {i0, i1, i2};

        float Px[3], Py[3], zs[3];
#pragma unroll
        for (int k = 0; k < 3; k++) {
            float x = verts[3 * idx[k] + 0];
            float y = verts[3 * idx[k] + 1];
            float z = verts[3 * idx[k] + 2];
            float vx = -x, vy = -y, vz = z;      // R = diag(-1,-1,1)
            zs[k] = vz;
            float zz = fmaxf(vz, 1e-6f);
            Px[k] = (1000.0f * vx / zz + 512.0f) / 1024.0f * (float)WIMG;
            Py[k] = (1000.0f * vy / zz + 512.0f) / 1024.0f * (float)HIMG;
        }
        float tz = (zs[0] + zs[1] + zs[2]) * (1.0f / 3.0f);

        FaceData fd;
        fd.ax = Px[0]; fd.ay = Py[0];
        fd.bx = Px[1]; fd.by = Py[1];
        fd.cx = Px[2]; fd.cy = Py[2];
        fd.e0x = fd.bx - fd.ax; fd.e0y = fd.by - fd.ay;
        fd.e1x = fd.cx - fd.bx; fd.e1y = fd.cy - fd.by;
        fd.e2x = fd.ax - fd.cx; fd.e2y = fd.ay - fd.cy;
        fd.rd0 = 1.0f / (fd.e0x * fd.e0x + fd.e0y * fd.e0y + 1e-12f);
        fd.rd1 = 1.0f / (fd.e1x * fd.e1x + fd.e1y * fd.e1y + 1e-12f);
        fd.rd2 = 1.0f / (fd.e2x * fd.e2x + fd.e2y * fd.e2y + 1e-12f);

        if (!(tz > 1e-6f)) {
            fd.x0 = 1; fd.x1 = 0; fd.y0 = 1; fd.y1 = 0;
        } else {
            float minx = fminf(fd.ax, fminf(fd.bx, fd.cx));
            float maxx = fmaxf(fd.ax, fmaxf(fd.bx, fd.cx));
            float miny = fminf(fd.ay, fminf(fd.by, fd.cy));
            float maxy = fmaxf(fd.ay, fmaxf(fd.by, fd.cy));
            int x0 = max(0, (int)floorf(minx) - 1);
            int x1 = min(WIMG - 1, (int)ceilf(maxx));
            int y0 = max(0, (int)floorf(miny) - 1);
            int y1 = min(HIMG - 1, (int)ceilf(maxy));
            bool pointdeg = (fd.e0x == 0.0f && fd.e0y == 0.0f &&
                             fd.e1x == 0.0f && fd.e1y == 0.0f);
            if (pointdeg) { x0 = 0; x1 = WIMG - 1; y0 = 0; y1 = HIMG - 1; }
            fd.x0 = x0; fd.x1 = x1; fd.y0 = y0; fd.y1 = y1;
        }
        g_face[f] = fd;
    }

    grid_barrier(base, 1);

    // ---------------- Phase 2: face-major rasterization --------------------
    for (int f = bid; f < NF; f += NB) {
        const FaceData fd = g_face[f];
        int w = fd.x1 - fd.x0 + 1;
        int h = fd.y1 - fd.y0 + 1;
        if (w <= 0 || h <= 0) continue;
        int n = w * h;

        for (int i = tid; i < n; i += NT) {
            int ix = fd.x0 + (i % w);
            int iy = fd.y0 + (i / w);
            float px = (float)ix + 0.5f;
            float py = (float)iy + 0.5f;

            float apx0 = px - fd.ax, apy0 = py - fd.ay;
            float apx1 = px - fd.bx, apy1 = py - fd.by;
            float apx2 = px - fd.cx, apy2 = py - fd.cy;

            float c0 = fd.e0x * apy0 - fd.e0y * apx0;
            float c1 = fd.e1x * apy1 - fd.e1y * apx1;
            float c2 = fd.e2x * apy2 - fd.e2y * apx2;
            bool inside = (c0 >= 0.0f && c1 >= 0.0f && c2 >= 0.0f) ||
                          (c0 <= 0.0f && c1 <= 0.0f && c2 <= 0.0f);

            float t0 = fminf(fmaxf((apx0 * fd.e0x + apy0 * fd.e0y) * fd.rd0, 0.0f), 1.0f);
            float rx = apx0 - t0 * fd.e0x;
            float ry = apy0 - t0 * fd.e0y;
            float d2min = rx * rx + ry * ry;

            float t1 = fminf(fmaxf((apx1 * fd.e1x + apy1 * fd.e1y) * fd.rd1, 0.0f), 1.0f);
            rx = apx1 - t1 * fd.e1x;
            ry = apy1 - t1 * fd.e1y;
            d2min = fminf(d2min, rx * rx + ry * ry);

            float t2 = fminf(fmaxf((apx2 * fd.e2x + apy2 * fd.e2y) * fd.rd2, 0.0f), 1.0f);
            rx = apx2 - t2 * fd.e2x;
            ry = apy2 - t2 * fd.e2y;
            d2min = fminf(d2min, rx * rx + ry * ry);

            if (inside || d2min <= BLURF) {
                float u = (inside ? d2min : -d2min) * INV_SIGMA;
                // log1p(-sigmoid(u)) == -softplus(u)
                float sp = (u > 15.0f) ? u : log1pf(__expf(u));
                if (sp != 0.0f) atomicAdd(&g_sum[iy * WIMG + ix], -sp);
            }
        }
    }

    grid_barrier(base, 2);

    // ---------------- Phase 3: finalize + per-block loss partial -----------
    float local = 0.0f;
    if (gtid < HW) {
        float alpha = 1.0f - expf(g_sum[gtid]);
        out[1 + gtid] = alpha;
        local = fabsf(alpha - gt[gtid]);
    }
    float psum = block_reduce(local, ws);
    if (tid == 0) g_partial[bid] = psum;

    grid_barrier(base, 3);

    // ---------------- Phase 4: block 0 reduces partials to loss ------------
    if (bid == 0) {
        float v = (tid < NB) ? g_partial[tid] : 0.0f;
        float total = block_reduce(v, ws);
        if (tid == 0) out[0] = total * (1.0f / (float)HW);
    }
}

extern "C" void kernel_launch(void* const* d_in, const int* in_sizes, int n_in,
                              void* d_out, int out_size) {
    const float* verts = nullptr;
    const float* gt    = nullptr;
    const int*   faces = nullptr;
    for (int i = 0; i < n_in; i++) {
        if (in_sizes[i] == NV * 3)      verts = (const float*)d_in[i];
        else if (in_sizes[i] == HW)     gt    = (const float*)d_in[i];
        else if (in_sizes[i] == NF * 3) faces = (const int*)d_in[i];
    }
    float* out = (float*)d_out;
    (void)out_size;
    fused_kernel<<<NB, NT>>>(verts, faces, gt, out);
}

// round 3
// speedup vs baseline: 1.0536x; 1.0536x over previous
#include <cuda_runtime.h>
#include <cuda_bf16.h>

#define HIMG 240
#define WIMG 135
#define HW   (HIMG * WIMG)
#define NF   1000
#define NV   600
#define INV_SIGMA 1.0e4f
#define BLURF 9.210240366975849e-4f

#define NT   512          // threads per block (16 warps)

__device__ float    g_sum[HW];   // zero at module load; finalizer re-zeros
__device__ unsigned g_done = 0;  // completion counter; last block resets

__global__ void __launch_bounds__(NT)
silhouette_kernel(const float* __restrict__ verts,
                  const int*   __restrict__ faces,
                  const float* __restrict__ gt,
                  float* __restrict__ out /* [0]=loss, [1..]=sil */) {
    const int tid  = threadIdx.x;
    const int lane = tid & 31;
    const int warp = tid >> 5;           // 0..15
    const int f    = blockIdx.x;

    // ---------------- Per-face setup (redundant per thread, no sync) -------
    int i0 = faces[3 * f + 0];
    int i1 = faces[3 * f + 1];
    int i2 = faces[3 * f + 2];
    int idx[3] = {i0, i1, i2};

    float Px[3], Py[3], zs[3];
#pragma unroll
    for (int k = 0; k < 3; k++) {
        float x = verts[3 * idx[k] + 0];
        float y = verts[3 * idx[k] + 1];
        float z = verts[3 * idx[k] + 2];
        float vx = -x, vy = -y, vz = z;          // R = diag(-1,-1,1)
        zs[k] = vz;
        float zz = fmaxf(vz, 1e-6f);
        Px[k] = (1000.0f * vx / zz + 512.0f) / 1024.0f * (float)WIMG;
        Py[k] = (1000.0f * vy / zz + 512.0f) / 1024.0f * (float)HIMG;
    }
    float tz = (zs[0] + zs[1] + zs[2]) * (1.0f / 3.0f);

    float ax = Px[0], ay = Py[0];
    float bx = Px[1], by = Py[1];
    float cx = Px[2], cy = Py[2];
    float e0x = bx - ax, e0y = by - ay;
    float e1x = cx - bx, e1y = cy - by;
    float e2x = ax - cx, e2y = ay - cy;
    float rd0 = 1.0f / (e0x * e0x + e0y * e0y + 1e-12f);
    float rd1 = 1.0f / (e1x * e1x + e1y * e1y + 1e-12f);
    float rd2 = 1.0f / (e2x * e2x + e2y * e2y + 1e-12f);

    int x0, x1, y0, y1;
    if (!(tz > 1e-6f)) {
        x0 = 1; x1 = 0; y0 = 1; y1 = 0;          // face culled
    } else {
        float minx = fminf(ax, fminf(bx, cx));
        float maxx = fmaxf(ax, fmaxf(bx, cx));
        float miny = fminf(ay, fminf(by, cy));
        float maxy = fmaxf(ay, fmaxf(by, cy));
        x0 = max(0, (int)floorf(minx) - 1);
        x1 = min(WIMG - 1, (int)ceilf(maxx));
        y0 = max(0, (int)floorf(miny) - 1);
        y1 = min(HIMG - 1, (int)ceilf(maxy));
        bool pointdeg = (e0x == 0.0f && e0y == 0.0f &&
                         e1x == 0.0f && e1y == 0.0f);
        if (pointdeg) { x0 = 0; x1 = WIMG - 1; y0 = 0; y1 = HIMG - 1; }
    }

    // ---------------- Rasterize: warp = row sweep, lane = x sweep ----------
    for (int iy = y0 + warp; iy <= y1; iy += (NT >> 5)) {
        float py = (float)iy + 0.5f;
        for (int ix = x0 + lane; ix <= x1; ix += 32) {
            float px = (float)ix + 0.5f;

            float apx0 = px - ax, apy0 = py - ay;
            float apx1 = px - bx, apy1 = py - by;
            float apx2 = px - cx, apy2 = py - cy;

            float c0 = e0x * apy0 - e0y * apx0;
            float c1 = e1x * apy1 - e1y * apx1;
            float c2 = e2x * apy2 - e2y * apx2;
            bool inside = (c0 >= 0.0f && c1 >= 0.0f && c2 >= 0.0f) ||
                          (c0 <= 0.0f && c1 <= 0.0f && c2 <= 0.0f);

            float t0 = fminf(fmaxf((apx0 * e0x + apy0 * e0y) * rd0, 0.0f), 1.0f);
            float rx = apx0 - t0 * e0x;
            float ry = apy0 - t0 * e0y;
            float d2min = rx * rx + ry * ry;

            float t1 = fminf(fmaxf((apx1 * e1x + apy1 * e1y) * rd1, 0.0f), 1.0f);
            rx = apx1 - t1 * e1x;
            ry = apy1 - t1 * e1y;
            d2min = fminf(d2min, rx * rx + ry * ry);

            float t2 = fminf(fmaxf((apx2 * e2x + apy2 * e2y) * rd2, 0.0f), 1.0f);
            rx = apx2 - t2 * e2x;
            ry = apy2 - t2 * e2y;
            d2min = fminf(d2min, rx * rx + ry * ry);

            if (inside || d2min <= BLURF) {
                float u = (inside ? d2min : -d2min) * INV_SIGMA;
                // log1p(-sigmoid(u)) == -softplus(u)
                float sp = (u > 15.0f) ? u : log1pf(__expf(u));
                if (sp != 0.0f) atomicAdd(&g_sum[iy * WIMG + ix], -sp);
            }
        }
    }

    // ---------------- Last-block-done: finalize --------------------------
    __syncthreads();
    __threadfence();
    __shared__ bool s_last;
    if (tid == 0) {
        unsigned old = atomicAdd(&g_done, 1u);
        s_last = (old == (unsigned)(gridDim.x - 1));
        if (s_last) g_done = 0;            // reset for next graph replay
    }
    __syncthreads();

    if (s_last) {
        float local = 0.0f;
        for (int i = tid; i < HW; i += NT) {
            float s = __ldcg(&g_sum[i]);   // L2 path (REDs live there)
            __stcg(&g_sum[i], 0.0f);       // self-clean for next launch
            float alpha = 1.0f - expf(s);
            out[1 + i] = alpha;
            local += fabsf(alpha - gt[i]);
        }
        // block reduction (16 warps)
#pragma unroll
        for (int o = 16; o > 0; o >>= 1)
            local += __shfl_down_sync(0xffffffffu, local, o);
        __shared__ float ws[16];
        if (lane == 0) ws[warp] = local;
        __syncthreads();
        if (warp == 0) {
            float v = (lane < (NT >> 5)) ? ws[lane] : 0.0f;
#pragma unroll
            for (int o = 8; o > 0; o >>= 1)
                v += __shfl_down_sync(0xffffu, v, o);
            if (lane == 0) out[0] = v * (1.0f / (float)HW);
        }
    }
}

extern "C" void kernel_launch(void* const* d_in, const int* in_sizes, int n_in,
                              void* d_out, int out_size) {
    const float* verts = nullptr;
    const float* gt    = nullptr;
    const int*   faces = nullptr;
    for (int i = 0; i < n_in; i++) {
        if (in_sizes[i] == NV * 3)      verts = (const float*)d_in[i];
        else if (in_sizes[i] == HW)     gt    = (const float*)d_in[i];
        else if (in_sizes[i] == NF * 3) faces = (const int*)d_in[i];
    }
    float* out = (float*)d_out;
    (void)out_size;
    silhouette_kernel<<<NF, NT>>>(verts, faces, gt, out);
}

// round 4
// speedup vs baseline: 1.4441x; 1.3706x over previous
#include <cuda_runtime.h>
#include <cuda_bf16.h>

#define HIMG 240
#define WIMG 135
#define HW   (HIMG * WIMG)
#define NF   1000
#define NV   600
#define INV_SIGMA 1.0e4f
#define BLURF 9.210240366975849e-4f
#define BAND  0.05f          // px; inside & farther than this from all edges => alpha-saturating

#define NT 256               // raster block: 8 warps

__device__ float g_sum[HW];   // band accumulator; zero at load, finalize re-zeros
__device__ float g_flag[HW];  // "deep coverage" flag;   zero at load, finalize re-zeros

// ---------------------------------------------------------------------------
// Raster: one block per face. Bulk pixels: inside-test + conservative line-
// distance -> idempotent flag store. Band pixels: exact reference math.
// ---------------------------------------------------------------------------
__global__ void __launch_bounds__(NT)
raster_kernel(const float* __restrict__ verts,
              const int*   __restrict__ faces,
              float* __restrict__ out) {
    const int tid  = threadIdx.x;
    const int lane = tid & 31;
    const int warp = tid >> 5;          // 0..7
    const int f    = blockIdx.x;

    if (f == 0 && tid == 0) out[0] = 0.0f;   // loss accumulator for finalize

    // ---- per-face setup (redundant per thread; fast paths) ----
    int i0 = faces[3 * f + 0];
    int i1 = faces[3 * f + 1];
    int i2 = faces[3 * f + 2];
    int idx[3] = {i0, i1, i2};

    float Px[3], Py[3], zs[3];
#pragma unroll
    for (int k = 0; k < 3; k++) {
        float x = verts[3 * idx[k] + 0];
        float y = verts[3 * idx[k] + 1];
        float z = verts[3 * idx[k] + 2];
        float vx = -x, vy = -y, vz = z;       // R = diag(-1,-1,1)
        zs[k] = vz;
        float zz = fmaxf(vz, 1e-6f);
        Px[k] = (__fdividef(1000.0f * vx, zz) + 512.0f) * ((float)WIMG / 1024.0f);
        Py[k] = (__fdividef(1000.0f * vy, zz) + 512.0f) * ((float)HIMG / 1024.0f);
    }
    float tz = (zs[0] + zs[1] + zs[2]) * (1.0f / 3.0f);
    if (!(tz > 1e-6f)) return;                // culled face

    float ax = Px[0], ay = Py[0];
    float bx = Px[1], by = Py[1];
    float cx = Px[2], cy = Py[2];
    float e0x = bx - ax, e0y = by - ay;
    float e1x = cx - bx, e1y = cy - by;
    float e2x = ax - cx, e2y = ay - cy;
    float l0 = e0x * e0x + e0y * e0y + 1e-12f;
    float l1 = e1x * e1x + e1y * e1y + 1e-12f;
    float l2 = e2x * e2x + e2y * e2y + 1e-12f;
    float rl0 = rsqrtf(l0), rl1 = rsqrtf(l1), rl2 = rsqrtf(l2);
    float rd0 = rl0 * rl0, rd1 = rl1 * rl1, rd2 = rl2 * rl2;

    float minx = fminf(ax, fminf(bx, cx));
    float maxx = fmaxf(ax, fmaxf(bx, cx));
    float miny = fminf(ay, fminf(by, cy));
    float maxy = fmaxf(ay, fmaxf(by, cy));
    int x0 = max(0, (int)floorf(minx) - 1);
    int x1 = min(WIMG - 1, (int)ceilf(maxx));
    int y0 = max(0, (int)floorf(miny) - 1);
    int y1 = min(HIMG - 1, (int)ceilf(maxy));
    // Fully degenerate point-face: reference treats all pixels as inside.
    if (e0x == 0.0f && e0y == 0.0f && e1x == 0.0f && e1y == 0.0f) {
        x0 = 0; x1 = WIMG - 1; y0 = 0; y1 = HIMG - 1;
    }

    // ---- sweep: warp = row, lane = column ----
    for (int iy = y0 + warp; iy <= y1; iy += (NT >> 5)) {
        float py = (float)iy + 0.5f;
        for (int ix = x0 + lane; ix <= x1; ix += 32) {
            float px = (float)ix + 0.5f;

            float apx0 = px - ax, apy0 = py - ay;
            float apx1 = px - bx, apy1 = py - by;
            float apx2 = px - cx, apy2 = py - cy;

            float c0 = e0x * apy0 - e0y * apx0;
            float c1 = e1x * apy1 - e1y * apx1;
            float c2 = e2x * apy2 - e2y * apx2;
            bool inside = (c0 >= 0.0f && c1 >= 0.0f && c2 >= 0.0f) ||
                          (c0 <= 0.0f && c1 <= 0.0f && c2 <= 0.0f);

            // conservative perpendicular distance to nearest edge LINE
            float dl = fminf(fabsf(c0) * rl0,
                       fminf(fabsf(c1) * rl1, fabsf(c2) * rl2));

            if (inside && dl > BAND) {
                // contribution <= -25 in log space: alpha saturates to 1.
                // Idempotent -> plain store, no atomic, no transcendental.
                g_flag[iy * WIMG + ix] = 1.0f;
            } else if (inside || dl <= BAND) {
                // exact reference math (segment distances)
                float t0 = fminf(fmaxf((apx0 * e0x + apy0 * e0y) * rd0, 0.0f), 1.0f);
                float rx = apx0 - t0 * e0x;
                float ry = apy0 - t0 * e0y;
                float d2min = rx * rx + ry * ry;

                float t1 = fminf(fmaxf((apx1 * e1x + apy1 * e1y) * rd1, 0.0f), 1.0f);
                rx = apx1 - t1 * e1x;
                ry = apy1 - t1 * e1y;
                d2min = fminf(d2min, rx * rx + ry * ry);

                float t2 = fminf(fmaxf((apx2 * e2x + apy2 * e2y) * rd2, 0.0f), 1.0f);
                rx = apx2 - t2 * e2x;
                ry = apy2 - t2 * e2y;
                d2min = fminf(d2min, rx * rx + ry * ry);

                if (inside || d2min <= BLURF) {
                    float u = (inside ? d2min : -d2min) * INV_SIGMA;
                    // log1p(-sigmoid(u)) == -softplus(u)
                    float sp = (u > 15.0f) ? u : log1pf(__expf(u));
                    if (sp != 0.0f) atomicAdd(&g_sum[iy * WIMG + ix], -sp);
                }
            }
            // outside & dl > BAND: segment dist >= line dist > BAND
            // => d2min > 2.5e-3 > BLURF => invalid in reference. Skip.
        }
    }
}

// ---------------------------------------------------------------------------
// Finalize: alpha, sil, loss; self-clean accumulators for next graph replay.
// ---------------------------------------------------------------------------
__global__ void __launch_bounds__(256)
finalize_kernel(const float* __restrict__ gt,
                float* __restrict__ out) {
    int i = blockIdx.x * blockDim.x + threadIdx.x;
    float local = 0.0f;
    if (i < HW) {
        float s  = g_sum[i];
        float fl = g_flag[i];
        g_sum[i]  = 0.0f;
        g_flag[i] = 0.0f;
        float alpha = (fl != 0.0f) ? 1.0f : (1.0f - expf(s));
        out[1 + i] = alpha;
        local = fabsf(alpha - gt[i]);
    }
#pragma unroll
    for (int o = 16; o > 0; o >>= 1)
        local += __shfl_down_sync(0xffffffffu, local, o);

    __shared__ float ws[8];
    int lane = threadIdx.x & 31;
    int wid  = threadIdx.x >> 5;
    if (lane == 0) ws[wid] = local;
    __syncthreads();
    if (wid == 0) {
        local = (lane < 8) ? ws[lane] : 0.0f;
#pragma unroll
        for (int o = 4; o > 0; o >>= 1)
            local += __shfl_down_sync(0xffu, local, o);
        if (lane == 0)
            atomicAdd(out, local * (1.0f / (float)HW));
    }
}

// ---------------------------------------------------------------------------
extern "C" void kernel_launch(void* const* d_in, const int* in_sizes, int n_in,
                              void* d_out, int out_size) {
    const float* verts = nullptr;
    const float* gt    = nullptr;
    const int*   faces = nullptr;
    for (int i = 0; i < n_in; i++) {
        if (in_sizes[i] == NV * 3)      verts = (const float*)d_in[i];
        else if (in_sizes[i] == HW)     gt    = (const float*)d_in[i];
        else if (in_sizes[i] == NF * 3) faces = (const int*)d_in[i];
    }
    float* out = (float*)d_out;
    (void)out_size;
    raster_kernel<<<NF, NT>>>(verts, faces, out);
    finalize_kernel<<<(HW + 255) / 256, 256>>>(gt, out);
}

// round 5
// speedup vs baseline: 1.7256x; 1.1950x over previous
#include <cuda_runtime.h>
#include <cuda_bf16.h>

#define HIMG 240
#define WIMG 135
#define HW   (HIMG * WIMG)
#define NF   1000
#define NV   600
#define INV_SIGMA 1.0e4f
#define BLURF 9.210240366975849e-4f
#define BAND  0.05f

#define NT   128           // 4 warps per block
#define NBLK NF            // one block per face; all co-resident (>=8 blk/SM)

struct __align__(8) FD {
    float ax, ay, bx, by, cx, cy;
    float e0x, e0y, e1x, e1y, e2x, e2y;
    float rl0, rl1, rl2, rd0, rd1, rd2;
    int x0, x1, y0, y1;
    int skip;
};

__device__ float    g_sum[HW];    // zero at load; finalize self-cleans
__device__ float    g_flag[HW];   // zero at load; finalize self-cleans
__device__ unsigned g_count   = 0;  // self-resets at barrier
__device__ unsigned g_release = 0;  // monotonic across graph replays

__device__ __forceinline__ void grid_barrier(unsigned base, unsigned r) {
    __syncthreads();
    if (threadIdx.x == 0) {
        __threadfence();
        unsigned old = atomicAdd(&g_count, 1);
        if (old == NBLK - 1) {
            g_count = 0;
            __threadfence();
            atomicAdd(&g_release, 1);
        } else {
            while (atomicAdd(&g_release, 0) - base < r) { }
        }
        __threadfence();
    }
    __syncthreads();
}

__global__ void __launch_bounds__(NT, 8)
silhouette_fused(const float* __restrict__ verts,
                 const int*   __restrict__ faces,
                 const float* __restrict__ gt,
                 float* __restrict__ out /* [0]=loss, [1..]=sil */) {
    __shared__ FD       sfd;
    __shared__ unsigned s_base;
    __shared__ float    ws[4];

    const int tid  = threadIdx.x;
    const int lane = tid & 31;
    const int warp = tid >> 5;        // 0..3
    const int f    = blockIdx.x;

    // ------------- Setup: ONE thread per block, broadcast via smem --------
    if (tid == 0) {
        s_base = atomicAdd(&g_release, 0u);    // per-launch barrier base
        if (f == 0) out[0] = 0.0f;             // loss accumulator

        int idx[3];
        idx[0] = faces[3 * f + 0];
        idx[1] = faces[3 * f + 1];
        idx[2] = faces[3 * f + 2];

        float Px[3], Py[3], zs[3];
#pragma unroll
        for (int k = 0; k < 3; k++) {
            float x = verts[3 * idx[k] + 0];
            float y = verts[3 * idx[k] + 1];
            float z = verts[3 * idx[k] + 2];
            float vx = -x, vy = -y, vz = z;    // R = diag(-1,-1,1)
            zs[k] = vz;
            float zz = fmaxf(vz, 1e-6f);
            Px[k] = (__fdividef(1000.0f * vx, zz) + 512.0f) * ((float)WIMG / 1024.0f);
            Py[k] = (__fdividef(1000.0f * vy, zz) + 512.0f) * ((float)HIMG / 1024.0f);
        }
        float tz = (zs[0] + zs[1] + zs[2]) * (1.0f / 3.0f);

        FD fd;
        fd.ax = Px[0]; fd.ay = Py[0];
        fd.bx = Px[1]; fd.by = Py[1];
        fd.cx = Px[2]; fd.cy = Py[2];
        fd.e0x = fd.bx - fd.ax; fd.e0y = fd.by - fd.ay;
        fd.e1x = fd.cx - fd.bx; fd.e1y = fd.cy - fd.by;
        fd.e2x = fd.ax - fd.cx; fd.e2y = fd.ay - fd.cy;
        float l0 = fd.e0x * fd.e0x + fd.e0y * fd.e0y + 1e-12f;
        float l1 = fd.e1x * fd.e1x + fd.e1y * fd.e1y + 1e-12f;
        float l2 = fd.e2x * fd.e2x + fd.e2y * fd.e2y + 1e-12f;
        fd.rl0 = rsqrtf(l0); fd.rl1 = rsqrtf(l1); fd.rl2 = rsqrtf(l2);
        fd.rd0 = fd.rl0 * fd.rl0; fd.rd1 = fd.rl1 * fd.rl1; fd.rd2 = fd.rl2 * fd.rl2;

        fd.skip = !(tz > 1e-6f);
        if (!fd.skip) {
            float minx = fminf(fd.ax, fminf(fd.bx, fd.cx));
            float maxx = fmaxf(fd.ax, fmaxf(fd.bx, fd.cx));
            float miny = fminf(fd.ay, fminf(fd.by, fd.cy));
            float maxy = fmaxf(fd.ay, fmaxf(fd.by, fd.cy));
            fd.x0 = max(0, (int)floorf(minx) - 1);
            fd.x1 = min(WIMG - 1, (int)ceilf(maxx));
            fd.y0 = max(0, (int)floorf(miny) - 1);
            fd.y1 = min(HIMG - 1, (int)ceilf(maxy));
            // fully-degenerate point face: reference marks all pixels inside
            if (fd.e0x == 0.0f && fd.e0y == 0.0f &&
                fd.e1x == 0.0f && fd.e1y == 0.0f) {
                fd.x0 = 0; fd.x1 = WIMG - 1; fd.y0 = 0; fd.y1 = HIMG - 1;
            }
        } else {
            fd.x0 = 1; fd.x1 = 0; fd.y0 = 1; fd.y1 = 0;
        }
        sfd = fd;
    }
    __syncthreads();
    const unsigned base = s_base;
    const FD fd = sfd;

    // ------------- Phase 1: rasterize this block's face -------------------
    if (!fd.skip) {
        for (int iy = fd.y0 + warp; iy <= fd.y1; iy += (NT >> 5)) {
            float py  = (float)iy + 0.5f;
            int   row = iy * WIMG;
            for (int ix = fd.x0 + lane; ix <= fd.x1; ix += 32) {
                float px = (float)ix + 0.5f;

                float apx0 = px - fd.ax, apy0 = py - fd.ay;
                float apx1 = px - fd.bx, apy1 = py - fd.by;
                float apx2 = px - fd.cx, apy2 = py - fd.cy;

                float c0 = fd.e0x * apy0 - fd.e0y * apx0;
                float c1 = fd.e1x * apy1 - fd.e1y * apx1;
                float c2 = fd.e2x * apy2 - fd.e2y * apx2;
                bool inside = (c0 >= 0.0f && c1 >= 0.0f && c2 >= 0.0f) ||
                              (c0 <= 0.0f && c1 <= 0.0f && c2 <= 0.0f);

                float dl = fminf(fabsf(c0) * fd.rl0,
                           fminf(fabsf(c1) * fd.rl1, fabsf(c2) * fd.rl2));

                if (inside && dl > BAND) {
                    // log-contribution <= -25 -> alpha saturates to 1.
                    g_flag[row + ix] = 1.0f;           // idempotent store
                } else if (inside || dl <= BAND) {
                    float t0 = fminf(fmaxf((apx0 * fd.e0x + apy0 * fd.e0y) * fd.rd0, 0.0f), 1.0f);
                    float rx = apx0 - t0 * fd.e0x;
                    float ry = apy0 - t0 * fd.e0y;
                    float d2min = rx * rx + ry * ry;

                    float t1 = fminf(fmaxf((apx1 * fd.e1x + apy1 * fd.e1y) * fd.rd1, 0.0f), 1.0f);
                    rx = apx1 - t1 * fd.e1x;
                    ry = apy1 - t1 * fd.e1y;
                    d2min = fminf(d2min, rx * rx + ry * ry);

                    float t2 = fminf(fmaxf((apx2 * fd.e2x + apy2 * fd.e2y) * fd.rd2, 0.0f), 1.0f);
                    rx = apx2 - t2 * fd.e2x;
                    ry = apy2 - t2 * fd.e2y;
                    d2min = fminf(d2min, rx * rx + ry * ry);

                    if (inside || d2min <= BLURF) {
                        float u = (inside ? d2min : -d2min) * INV_SIGMA;
                        // log1p(-sigmoid(u)) == -softplus(u)
                        float sp = (u > 15.0f) ? u : log1pf(__expf(u));
                        if (sp != 0.0f) atomicAdd(&g_sum[row + ix], -sp);
                    }
                }
                // outside & dl > BAND: d2min >= dl^2 > BLURF -> invalid. Skip.
            }
        }
    }

    // ------------- Grid barrier (all raster writes visible) ---------------
    grid_barrier(base, 1);

    // ------------- Phase 2: finalize, 1 pixel per thread ------------------
    int i = f * NT + tid;                 // blocks 0..253 carry pixels
    float local = 0.0f;
    if (i < HW) {
        float s  = g_sum[i];
        float fl = g_flag[i];
        g_sum[i]  = 0.0f;                 // self-clean for next replay
        g_flag[i] = 0.0f;
        float alpha = (fl != 0.0f) ? 1.0f : (1.0f - expf(s));
        out[1 + i] = alpha;
        local = fabsf(alpha - gt[i]);
    }
    if (f * NT < HW) {                    // only blocks with pixels reduce
#pragma unroll
        for (int o = 16; o > 0; o >>= 1)
            local += __shfl_down_sync(0xffffffffu, local, o);
        if (lane == 0) ws[warp] = local;
        __syncthreads();
        if (warp == 0) {
            float v = (lane < 4) ? ws[lane] : 0.0f;
#pragma unroll
            for (int o = 2; o > 0; o >>= 1)
                v += __shfl_down_sync(0xfu, v, o);
            if (lane == 0)
                atomicAdd(out, v * (1.0f / (float)HW));
        }
    }
}

extern "C" void kernel_launch(void* const* d_in, const int* in_sizes, int n_in,
                              void* d_out, int out_size) {
    const float* verts = nullptr;
    const float* gt    = nullptr;
    const int*   faces = nullptr;
    for (int i = 0; i < n_in; i++) {
        if (in_sizes[i] == NV * 3)      verts = (const float*)d_in[i];
        else if (in_sizes[i] == HW)     gt    = (const float*)d_in[i];
        else if (in_sizes[i] == NF * 3) faces = (const int*)d_in[i];
    }
    float* out = (float*)d_out;
    (void)out_size;
    silhouette_fused<<<NBLK, NT>>>(verts, faces, gt, out);
}